// round 2
// baseline (speedup 1.0000x reference)
#include <cuda_runtime.h>
#include <cstdint>
#include <math.h>

#define T_ 512
#define B_ 64
#define N_ 1024
#define G_ 4096   // 4*N

// ---------------- static device scratch (no allocations allowed) ----------------
__device__ float g_Pf[(size_t)T_ * B_ * G_];      // fwd pre-activations  [T][B][4N]
__device__ float g_Pb[(size_t)T_ * B_ * G_];      // bwd pre-activations
__device__ float g_Pc[(size_t)T_ * B_ * G_];      // cell pre-activations
__device__ float g_bi[(size_t)T_ * B_ * 2 * N_];  // bilstm output [T][B][2N]
__device__ float g_h[6][B_ * N_];                 // hf0 hf1 hb0 hb1 hc0 hc1
__device__ float g_c[3][B_ * N_];                 // cf cb cc

// grid-barrier state (count returns to 0 after every barrier; gen monotonic)
__device__ unsigned g_barc[2] = {0, 0};
__device__ unsigned g_barg[2] = {0, 0};

__device__ __forceinline__ void grid_barrier(int which, unsigned nb) {
    __syncthreads();
    if (threadIdx.x == 0) {
        __threadfence();
        volatile unsigned* gen = &g_barg[which];
        unsigned g = *gen;
        if (atomicAdd(&g_barc[which], 1) == nb - 1) {
            g_barc[which] = 0;
            __threadfence();
            atomicExch((unsigned*)gen, g + 1);
        } else {
            while (*gen == g) { __nanosleep(64); }
            __threadfence();
        }
    }
    __syncthreads();
}

// ---------------- zero the recurrent state ----------------
__global__ void zero_state_kernel() {
    int i = blockIdx.x * blockDim.x + threadIdx.x;
    if (i < 6 * B_ * N_) ((float*)g_h)[i] = 0.0f;
    if (i < 3 * B_ * N_) ((float*)g_c)[i] = 0.0f;
}

// ---------------- tf32 helpers ----------------
__device__ __forceinline__ uint32_t f2tf32(float x) {
    uint32_t r;
    asm("cvt.rna.tf32.f32 %0, %1;" : "=r"(r) : "f"(x));
    return r;
}

__device__ __forceinline__ void mma_tf32(float* c, const uint32_t* a, const uint32_t* b) {
    asm volatile(
        "mma.sync.aligned.m16n8k8.row.col.f32.tf32.tf32.f32 "
        "{%0,%1,%2,%3}, {%4,%5,%6,%7}, {%8,%9}, {%0,%1,%2,%3};"
        : "+f"(c[0]), "+f"(c[1]), "+f"(c[2]), "+f"(c[3])
        : "r"(a[0]), "r"(a[1]), "r"(a[2]), "r"(a[3]), "r"(b[0]), "r"(b[1]));
}

// ---------------- tf32 GEMM: C[m][g] = sum_k A[m][k]*W[g][k] + bias[g] ----------------
// BM=128, BN=64, BK=16. 256 threads (8 warps, 4x2), warp tile 32x32, mma m16n8k8.
// a_mode==1: logical m=(t*64+b) -> physical row (b*512+t) in Aext (inputs [B,T,N]).
// a_mode==0: A = Aext, row m directly. a_mode==2: A = g_bi, row m directly.
// dst_sel: 0 -> g_Pf, 1 -> g_Pb, 2 -> g_Pc.
__global__ __launch_bounds__(256) void gemm_tf32_kernel(
    const float* __restrict__ Aext,
    const float* __restrict__ W,
    const float* __restrict__ bias,
    int K, int a_mode, int dst_sel)
{
    float* C = (dst_sel == 0) ? g_Pf : (dst_sel == 1) ? g_Pb : g_Pc;
    const float* A = (a_mode == 2) ? (const float*)g_bi : Aext;

    __shared__ uint32_t As[128 * 20];  // [m][k], pad 20
    __shared__ uint32_t Ws[64 * 20];   // [g][k], pad 20

    const int tid = threadIdx.x;
    const int m0 = blockIdx.y * 128;
    const int g0 = blockIdx.x * 64;

    // A loaders: 128 rows x 16 k = 512 float4 -> 2 per thread
    const float* aptr[2];
    int arow[2];
    int akq[2];
#pragma unroll
    for (int i = 0; i < 2; i++) {
        int idx = tid + 256 * i;
        int r = idx >> 2;
        int kq = idx & 3;
        int m = m0 + r;
        int prow = (a_mode == 1) ? ((m & 63) * T_ + (m >> 6)) : m;
        aptr[i] = A + (size_t)prow * K + kq * 4;
        arow[i] = r;
        akq[i] = kq;
    }
    // W loader: 64 rows x 16 k = 256 float4 -> 1 per thread
    const int wr = tid >> 2;
    const int wkq = tid & 3;
    const float* wptr = W + (size_t)(g0 + wr) * K + wkq * 4;

    const int lane = tid & 31;
    const int wid = tid >> 5;
    const int gid = lane >> 2;
    const int tig = lane & 3;
    const int wm = (wid & 3) * 32;
    const int wn = (wid >> 2) * 32;

    float acc[2][4][4];
#pragma unroll
    for (int mf = 0; mf < 2; mf++)
#pragma unroll
        for (int nf = 0; nf < 4; nf++)
#pragma unroll
            for (int j = 0; j < 4; j++) acc[mf][nf][j] = 0.0f;

    for (int k0 = 0; k0 < K; k0 += 16) {
#pragma unroll
        for (int i = 0; i < 2; i++) {
            float4 v = *(const float4*)(aptr[i] + k0);
            uint4 u;
            u.x = f2tf32(v.x); u.y = f2tf32(v.y); u.z = f2tf32(v.z); u.w = f2tf32(v.w);
            *(uint4*)&As[arow[i] * 20 + akq[i] * 4] = u;
        }
        {
            float4 v = *(const float4*)(wptr + k0);
            uint4 u;
            u.x = f2tf32(v.x); u.y = f2tf32(v.y); u.z = f2tf32(v.z); u.w = f2tf32(v.w);
            *(uint4*)&Ws[wr * 20 + wkq * 4] = u;
        }
        __syncthreads();

#pragma unroll
        for (int ks = 0; ks < 2; ks++) {
            const int kb = ks * 8;
            uint32_t af[2][4];
#pragma unroll
            for (int mf = 0; mf < 2; mf++) {
                int mb = wm + mf * 16;
                af[mf][0] = As[(mb + gid) * 20 + kb + tig];
                af[mf][1] = As[(mb + gid + 8) * 20 + kb + tig];
                af[mf][2] = As[(mb + gid) * 20 + kb + tig + 4];
                af[mf][3] = As[(mb + gid + 8) * 20 + kb + tig + 4];
            }
            uint32_t bf[4][2];
#pragma unroll
            for (int nf = 0; nf < 4; nf++) {
                int nb = wn + nf * 8 + gid;
                bf[nf][0] = Ws[nb * 20 + kb + tig];
                bf[nf][1] = Ws[nb * 20 + kb + tig + 4];
            }
#pragma unroll
            for (int mf = 0; mf < 2; mf++)
#pragma unroll
                for (int nf = 0; nf < 4; nf++)
                    mma_tf32(acc[mf][nf], af[mf], bf[nf]);
        }
        __syncthreads();
    }

    // epilogue: bias + store
#pragma unroll
    for (int mf = 0; mf < 2; mf++) {
#pragma unroll
        for (int nf = 0; nf < 4; nf++) {
            int row = m0 + wm + mf * 16 + gid;
            int col = g0 + wn + nf * 8 + 2 * tig;
            float b0 = bias[col], b1 = bias[col + 1];
            float2 v0 = make_float2(acc[mf][nf][0] + b0, acc[mf][nf][1] + b1);
            float2 v1 = make_float2(acc[mf][nf][2] + b0, acc[mf][nf][3] + b1);
            *(float2*)&C[(size_t)row * G_ + col] = v0;
            *(float2*)&C[(size_t)(row + 8) * G_ + col] = v1;
        }
    }
}

// ---------------- persistent bilstm recurrence ----------------
// 128 blocks x 512 threads. Block b: dir = b>>6, unit tile u0 = (b&63)*16.
// Per step: gates[64 b][64 cols] where col = gate*16 + u.
__global__ __launch_bounds__(512, 1) void bilstm_persistent_kernel(
    const float* __restrict__ Wf_hh, const float* __restrict__ Wb_hh)
{
    __shared__ float h_s[16][68];
    __shared__ float w_s[16][68];
    __shared__ float gates[64][68];

    const int dir = blockIdx.x >> 6;
    const int u0 = (blockIdx.x & 63) * 16;
    const float* W = dir ? Wb_hh : Wf_hh;
    const float* Pbase = dir ? g_Pb : g_Pf;
    float* c = g_c[dir];

    const int tid = threadIdx.x;
    const int lk = tid & 15;
    const int bq = tid >> 4;           // 0..31 (loader)
    const int ty = tid >> 4;           // 0..31 -> batches 2ty, 2ty+1
    const int tx = tid & 15;           // cols 4tx..4tx+3

    // weight row pointers (fixed across steps)
    const float* wrow[2];
#pragma unroll
    for (int i = 0; i < 2; i++) {
        int cidx = bq + 32 * i;        // col 0..63
        int gate = cidx >> 4;
        int u = cidx & 15;
        wrow[i] = W + (size_t)(gate * N_ + u0 + u) * N_;
    }

    for (int s = 0; s < T_; s++) {
        const int t = dir ? (T_ - 1 - s) : s;
        const float* P = Pbase + (size_t)t * B_ * G_;
        const float* h_prev = g_h[2 * dir + (s & 1)];
        float* h_next = g_h[2 * dir + ((s + 1) & 1)];
        float* hist = g_bi + (size_t)t * B_ * 2 * N_ + dir * N_;

        float acc[2][4];
#pragma unroll
        for (int i = 0; i < 2; i++)
#pragma unroll
            for (int j = 0; j < 4; j++) acc[i][j] = 0.0f;

        for (int k0 = 0; k0 < N_; k0 += 16) {
            h_s[lk][bq]      = h_prev[(size_t)bq * N_ + k0 + lk];
            h_s[lk][bq + 32] = h_prev[(size_t)(bq + 32) * N_ + k0 + lk];
            w_s[lk][bq]      = wrow[0][k0 + lk];
            w_s[lk][bq + 32] = wrow[1][k0 + lk];
            __syncthreads();
#pragma unroll
            for (int kk = 0; kk < 16; kk++) {
                float2 a = *(const float2*)(&h_s[kk][ty * 2]);
                float4 w = *(const float4*)(&w_s[kk][tx * 4]);
                acc[0][0] += a.x * w.x; acc[0][1] += a.x * w.y; acc[0][2] += a.x * w.z; acc[0][3] += a.x * w.w;
                acc[1][0] += a.y * w.x; acc[1][1] += a.y * w.y; acc[1][2] += a.y * w.z; acc[1][3] += a.y * w.w;
            }
            __syncthreads();
        }

#pragma unroll
        for (int i = 0; i < 2; i++)
#pragma unroll
            for (int j = 0; j < 4; j++)
                gates[ty * 2 + i][tx * 4 + j] = acc[i][j];
        __syncthreads();

        // activation + state: 64 b x 16 u = 1024 pairs -> 2 per thread
#pragma unroll
        for (int i = 0; i < 2; i++) {
            int p = tid + 512 * i;
            int bl = p >> 4;
            int u = p & 15;
            int ug = u0 + u;
            const float* Pb = P + (size_t)bl * G_;
            float ig = gates[bl][u]      + Pb[ug];
            float fg = gates[bl][16 + u] + Pb[N_ + ug];
            float gg = gates[bl][32 + u] + Pb[2 * N_ + ug];
            float og = gates[bl][48 + u] + Pb[3 * N_ + ug];
            ig = 1.0f / (1.0f + expf(-ig));
            fg = 1.0f / (1.0f + expf(-fg));
            gg = tanhf(gg);
            og = 1.0f / (1.0f + expf(-og));
            size_t ci = (size_t)bl * N_ + ug;
            float cn = fg * c[ci] + ig * gg;
            c[ci] = cn;
            float hn = og * tanhf(cn);
            h_next[ci] = hn;
            hist[(size_t)bl * 2 * N_ + ug] = hn;
        }
        grid_barrier(0, 128);
    }
}

// ---------------- persistent cell recurrence ----------------
// 128 blocks x 256 threads. Block owns 8 units (32 gate cols) x 64 batches.
// Writes enc_outputs [B,T,N] directly; copies (hT, cT) tail at the end.
__global__ __launch_bounds__(256, 1) void cell_persistent_kernel(
    const float* __restrict__ Wc_hh, float* __restrict__ out)
{
    __shared__ float h_s[16][68];
    __shared__ float w_s[16][36];
    __shared__ float gates[64][36];

    const int u0 = blockIdx.x * 8;
    float* c = g_c[2];

    const int tid = threadIdx.x;
    const int lk = tid & 15;
    const int bq = tid >> 4;           // 0..15 (loader)
    const int ty = tid >> 3;           // 0..31 -> batches 2ty, 2ty+1
    const int tx = tid & 7;            // cols 4tx..4tx+3

    // weight rows: 32 cols, 2 per thread's loader slots
    const float* wrow[2];
#pragma unroll
    for (int i = 0; i < 2; i++) {
        int cidx = bq + 16 * i;        // col 0..31
        int gate = cidx >> 3;
        int u = cidx & 7;
        wrow[i] = Wc_hh + (size_t)(gate * N_ + u0 + u) * N_;
    }

    for (int s = 0; s < T_; s++) {
        const float* P = g_Pc + (size_t)s * B_ * G_;
        const float* h_prev = g_h[4 + (s & 1)];
        float* h_next = g_h[4 + ((s + 1) & 1)];

        float acc[2][4];
#pragma unroll
        for (int i = 0; i < 2; i++)
#pragma unroll
            for (int j = 0; j < 4; j++) acc[i][j] = 0.0f;

        for (int k0 = 0; k0 < N_; k0 += 16) {
#pragma unroll
            for (int i = 0; i < 4; i++)
                h_s[lk][bq + 16 * i] = h_prev[(size_t)(bq + 16 * i) * N_ + k0 + lk];
            w_s[lk][bq]      = wrow[0][k0 + lk];
            w_s[lk][bq + 16] = wrow[1][k0 + lk];
            __syncthreads();
#pragma unroll
            for (int kk = 0; kk < 16; kk++) {
                float2 a = *(const float2*)(&h_s[kk][ty * 2]);
                float4 w = *(const float4*)(&w_s[kk][tx * 4]);
                acc[0][0] += a.x * w.x; acc[0][1] += a.x * w.y; acc[0][2] += a.x * w.z; acc[0][3] += a.x * w.w;
                acc[1][0] += a.y * w.x; acc[1][1] += a.y * w.y; acc[1][2] += a.y * w.z; acc[1][3] += a.y * w.w;
            }
            __syncthreads();
        }

#pragma unroll
        for (int i = 0; i < 2; i++)
#pragma unroll
            for (int j = 0; j < 4; j++)
                gates[ty * 2 + i][tx * 4 + j] = acc[i][j];
        __syncthreads();

        // activation: 64 b x 8 u = 512 pairs -> 2 per thread
#pragma unroll
        for (int i = 0; i < 2; i++) {
            int p = tid + 256 * i;
            int bl = p >> 3;
            int u = p & 7;
            int ug = u0 + u;
            const float* Pb = P + (size_t)bl * G_;
            float ig = gates[bl][u]      + Pb[ug];
            float fg = gates[bl][8 + u]  + Pb[N_ + ug];
            float gg = gates[bl][16 + u] + Pb[2 * N_ + ug];
            float og = gates[bl][24 + u] + Pb[3 * N_ + ug];
            ig = 1.0f / (1.0f + expf(-ig));
            fg = 1.0f / (1.0f + expf(-fg));
            gg = tanhf(gg);
            og = 1.0f / (1.0f + expf(-og));
            size_t ci = (size_t)bl * N_ + ug;
            float cn = fg * c[ci] + ig * gg;
            c[ci] = cn;
            float hn = og * tanhf(cn);
            h_next[ci] = hn;
            out[((size_t)bl * T_ + s) * N_ + ug] = hn;
        }
        grid_barrier(1, 128);
    }

    // tail: (hT, cT). Final h in g_h[4] (512 even), c in g_c[2].
    const size_t tail = (size_t)B_ * T_ * N_;
    const int HS = B_ * N_;
#pragma unroll
    for (int i = 0; i < 2; i++) {
        int idx = blockIdx.x * 256 + tid + 32768 * i;
        out[tail + idx] = g_h[4][idx];
        out[tail + HS + idx] = g_c[2][idx];
    }
}

// ---------------- host launcher ----------------
extern "C" void kernel_launch(void* const* d_in, const int* in_sizes, int n_in,
                              void* d_out, int out_size) {
    (void)in_sizes; (void)n_in; (void)out_size;
    const float* x     = (const float*)d_in[0];
    const float* Wf_ih = (const float*)d_in[1];
    const float* Wf_hh = (const float*)d_in[2];
    const float* bf    = (const float*)d_in[3];
    const float* Wb_ih = (const float*)d_in[4];
    const float* Wb_hh = (const float*)d_in[5];
    const float* bb    = (const float*)d_in[6];
    const float* Wc_ih = (const float*)d_in[7];
    const float* Wc_hh = (const float*)d_in[8];
    const float* bc    = (const float*)d_in[9];
    float* out = (float*)d_out;

    // 1) zero recurrent state
    zero_state_kernel<<<(6 * B_ * N_ + 511) / 512, 512>>>();

    // 2) input projections (tf32 tensor core)
    dim3 ggrid(G_ / 64, (T_ * B_) / 128);
    gemm_tf32_kernel<<<ggrid, 256>>>(x, Wf_ih, bf, N_, 1, 0);
    gemm_tf32_kernel<<<ggrid, 256>>>(x, Wb_ih, bb, N_, 1, 1);

    // 3) bilstm recurrence (persistent, both directions)
    bilstm_persistent_kernel<<<128, 512>>>(Wf_hh, Wb_hh);

    // 4) cell input projection over bilstm output (K = 2N)
    gemm_tf32_kernel<<<ggrid, 256>>>(nullptr, Wc_ih, bc, 2 * N_, 2, 2);

    // 5) cell recurrence (persistent) + output + tail
    cell_persistent_kernel<<<128, 256>>>(Wc_hh, out);
}

// round 3
// speedup vs baseline: 2.2637x; 2.2637x over previous
#include <cuda_runtime.h>
#include <cstdint>
#include <math.h>

#define T_ 512
#define B_ 64
#define N_ 1024
#define G_ 4096   // 4*N

// ---------------- static device scratch (no allocations allowed) ----------------
__device__ float g_Pf[(size_t)T_ * B_ * G_];      // fwd pre-activations  [T][B][4N]
__device__ float g_Pb[(size_t)T_ * B_ * G_];      // bwd pre-activations
__device__ float g_Pc[(size_t)T_ * B_ * G_];      // cell pre-activations
__device__ float g_bi[(size_t)T_ * B_ * 2 * N_];  // bilstm output [T][B][2N]
__device__ float g_h[6][B_ * N_];                 // hf0 hf1 hb0 hb1 hc0 hc1
__device__ float g_c[3][B_ * N_];                 // cf cb cc
__device__ uint32_t g_Wt[3][(size_t)G_ * N_];     // tf32 W_hh: fwd, bwd, cell

// grid-barrier state
__device__ unsigned g_barc[2] = {0, 0};
__device__ unsigned g_barg[2] = {0, 0};

__device__ __forceinline__ void grid_barrier(int which, unsigned nb) {
    __syncthreads();
    if (threadIdx.x == 0) {
        __threadfence();
        volatile unsigned* gen = &g_barg[which];
        unsigned g = *gen;
        if (atomicAdd(&g_barc[which], 1) == nb - 1) {
            g_barc[which] = 0;
            __threadfence();
            atomicExch((unsigned*)gen, g + 1);
        } else {
            while (*gen == g) { __nanosleep(64); }
            __threadfence();
        }
    }
    __syncthreads();
}

__global__ void zero_state_kernel() {
    int i = blockIdx.x * blockDim.x + threadIdx.x;
    if (i < 6 * B_ * N_) ((float*)g_h)[i] = 0.0f;
    if (i < 3 * B_ * N_) ((float*)g_c)[i] = 0.0f;
}

// ---------------- tf32 helpers ----------------
__device__ __forceinline__ uint32_t f2tf32(float x) {
    uint32_t r;
    asm("cvt.rna.tf32.f32 %0, %1;" : "=r"(r) : "f"(x));
    return r;
}

__device__ __forceinline__ void mma_tf32(float* c, const uint32_t* a, const uint32_t* b) {
    asm volatile(
        "mma.sync.aligned.m16n8k8.row.col.f32.tf32.tf32.f32 "
        "{%0,%1,%2,%3}, {%4,%5,%6,%7}, {%8,%9}, {%0,%1,%2,%3};"
        : "+f"(c[0]), "+f"(c[1]), "+f"(c[2]), "+f"(c[3])
        : "r"(a[0]), "r"(a[1]), "r"(a[2]), "r"(a[3]), "r"(b[0]), "r"(b[1]));
}

// ---------------- one-time weight conversion to tf32 ----------------
__global__ void wconv_kernel(const float* __restrict__ Wf,
                             const float* __restrict__ Wb,
                             const float* __restrict__ Wc) {
    const float* src = (blockIdx.y == 0) ? Wf : (blockIdx.y == 1) ? Wb : Wc;
    uint32_t* dst = g_Wt[blockIdx.y];
    size_t i = (size_t)blockIdx.x * blockDim.x + threadIdx.x;  // float4 index
    float4 v = ((const float4*)src)[i];
    uint4 u;
    u.x = f2tf32(v.x); u.y = f2tf32(v.y); u.z = f2tf32(v.z); u.w = f2tf32(v.w);
    ((uint4*)dst)[i] = u;
}

// ---------------- tf32 GEMM: C[m][g] = sum_k A[m][k]*W[g][k] + bias[g] ----------------
__global__ __launch_bounds__(256) void gemm_tf32_kernel(
    const float* __restrict__ Aext,
    const float* __restrict__ W,
    const float* __restrict__ bias,
    int K, int a_mode, int dst_sel)
{
    float* C = (dst_sel == 0) ? g_Pf : (dst_sel == 1) ? g_Pb : g_Pc;
    const float* A = (a_mode == 2) ? (const float*)g_bi : Aext;

    __shared__ uint32_t As[128 * 20];
    __shared__ uint32_t Ws[64 * 20];

    const int tid = threadIdx.x;
    const int m0 = blockIdx.y * 128;
    const int g0 = blockIdx.x * 64;

    const float* aptr[2];
    int arow[2], akq[2];
#pragma unroll
    for (int i = 0; i < 2; i++) {
        int idx = tid + 256 * i;
        int r = idx >> 2;
        int kq = idx & 3;
        int m = m0 + r;
        int prow = (a_mode == 1) ? ((m & 63) * T_ + (m >> 6)) : m;
        aptr[i] = A + (size_t)prow * K + kq * 4;
        arow[i] = r;
        akq[i] = kq;
    }
    const int wr = tid >> 2;
    const int wkq = tid & 3;
    const float* wptr = W + (size_t)(g0 + wr) * K + wkq * 4;

    const int lane = tid & 31;
    const int wid = tid >> 5;
    const int gid = lane >> 2;
    const int tig = lane & 3;
    const int wm = (wid & 3) * 32;
    const int wn = (wid >> 2) * 32;

    float acc[2][4][4];
#pragma unroll
    for (int mf = 0; mf < 2; mf++)
#pragma unroll
        for (int nf = 0; nf < 4; nf++)
#pragma unroll
            for (int j = 0; j < 4; j++) acc[mf][nf][j] = 0.0f;

    for (int k0 = 0; k0 < K; k0 += 16) {
#pragma unroll
        for (int i = 0; i < 2; i++) {
            float4 v = *(const float4*)(aptr[i] + k0);
            uint4 u;
            u.x = f2tf32(v.x); u.y = f2tf32(v.y); u.z = f2tf32(v.z); u.w = f2tf32(v.w);
            *(uint4*)&As[arow[i] * 20 + akq[i] * 4] = u;
        }
        {
            float4 v = *(const float4*)(wptr + k0);
            uint4 u;
            u.x = f2tf32(v.x); u.y = f2tf32(v.y); u.z = f2tf32(v.z); u.w = f2tf32(v.w);
            *(uint4*)&Ws[wr * 20 + wkq * 4] = u;
        }
        __syncthreads();

#pragma unroll
        for (int ks = 0; ks < 2; ks++) {
            const int kb = ks * 8;
            uint32_t af[2][4];
#pragma unroll
            for (int mf = 0; mf < 2; mf++) {
                int mb = wm + mf * 16;
                af[mf][0] = As[(mb + gid) * 20 + kb + tig];
                af[mf][1] = As[(mb + gid + 8) * 20 + kb + tig];
                af[mf][2] = As[(mb + gid) * 20 + kb + tig + 4];
                af[mf][3] = As[(mb + gid + 8) * 20 + kb + tig + 4];
            }
            uint32_t bf[4][2];
#pragma unroll
            for (int nf = 0; nf < 4; nf++) {
                int nb = wn + nf * 8 + gid;
                bf[nf][0] = Ws[nb * 20 + kb + tig];
                bf[nf][1] = Ws[nb * 20 + kb + tig + 4];
            }
#pragma unroll
            for (int mf = 0; mf < 2; mf++)
#pragma unroll
                for (int nf = 0; nf < 4; nf++)
                    mma_tf32(acc[mf][nf], af[mf], bf[nf]);
        }
        __syncthreads();
    }

#pragma unroll
    for (int mf = 0; mf < 2; mf++) {
#pragma unroll
        for (int nf = 0; nf < 4; nf++) {
            int row = m0 + wm + mf * 16 + gid;
            int col = g0 + wn + nf * 8 + 2 * tig;
            float b0 = bias[col], b1 = bias[col + 1];
            float2 v0 = make_float2(acc[mf][nf][0] + b0, acc[mf][nf][1] + b1);
            float2 v1 = make_float2(acc[mf][nf][2] + b0, acc[mf][nf][3] + b1);
            *(float2*)&C[(size_t)row * G_ + col] = v0;
            *(float2*)&C[(size_t)(row + 8) * G_ + col] = v1;
        }
    }
}

// ---------------- persistent bilstm recurrence (tensor core) ----------------
// 128 blocks x 256 threads. dir = bid>>6, u0 = (bid&63)*16 -> 64 gate cols.
// Per step: gates[64 batch][64 cols], col = gate*16+u. m64 n64 k1024 tf32 mma.
#define SPITCH 132
__global__ __launch_bounds__(256, 1) void bilstm_mma_kernel()
{
    extern __shared__ uint32_t smem_u[];
    uint32_t* hs = smem_u;                       // [64][132] tf32 h (batch-major)
    uint32_t* ws = smem_u + 64 * SPITCH;         // [64][132] tf32 W rows (col-major rows)
    float* gates = (float*)(smem_u + 2 * 64 * SPITCH);  // [64][68]

    const int bid = blockIdx.x;
    const int dir = bid >> 6;
    const int u0 = (bid & 63) * 16;
    const uint32_t* Wt = g_Wt[dir];
    const float* Pbase = dir ? g_Pb : g_Pf;
    float* c = g_c[dir];

    const int tid = threadIdx.x;
    const int lane = tid & 31;
    const int wid = tid >> 5;
    const int gid = lane >> 2;
    const int tig = lane & 3;
    const int wm = (wid & 1) * 32;
    const int wn = (wid >> 1) * 16;

    // loader geometry: idx = tid + 256*i -> row r = (tid>>5)+8i, quad q = tid&31
    const int r0 = tid >> 5;
    const int q = tid & 31;

    // W source pointers (static across steps): col c -> W row gate*N + u0 + u
    const uint32_t* wsrc[8];
#pragma unroll
    for (int i = 0; i < 8; i++) {
        int cc = r0 + 8 * i;
        int gate = cc >> 4;
        int u = cc & 15;
        wsrc[i] = Wt + (size_t)(gate * N_ + u0 + u) * N_ + q * 4;
    }

    for (int s = 0; s < T_; s++) {
        const int t = dir ? (T_ - 1 - s) : s;
        const float* P = Pbase + (size_t)t * B_ * G_;
        const float* h_prev = g_h[2 * dir + (s & 1)];
        float* h_next = g_h[2 * dir + ((s + 1) & 1)];
        float* hist = g_bi + (size_t)t * B_ * 2 * N_ + dir * N_;

        float acc[2][2][4];
#pragma unroll
        for (int mf = 0; mf < 2; mf++)
#pragma unroll
            for (int nf = 0; nf < 2; nf++)
#pragma unroll
                for (int j = 0; j < 4; j++) acc[mf][nf][j] = 0.0f;

        for (int k0 = 0; k0 < N_; k0 += 128) {
            // load h tile: 64 rows x 128 k
#pragma unroll
            for (int i = 0; i < 8; i++) {
                int r = r0 + 8 * i;
                float4 v = *(const float4*)(h_prev + (size_t)r * N_ + k0 + q * 4);
                uint4 u;
                u.x = f2tf32(v.x); u.y = f2tf32(v.y); u.z = f2tf32(v.z); u.w = f2tf32(v.w);
                *(uint4*)&hs[r * SPITCH + q * 4] = u;
            }
            // load W tile: 64 cols x 128 k (already tf32)
#pragma unroll
            for (int i = 0; i < 8; i++) {
                int cc = r0 + 8 * i;
                uint4 u = *(const uint4*)(wsrc[i] + k0);
                *(uint4*)&ws[cc * SPITCH + q * 4] = u;
            }
            __syncthreads();

#pragma unroll
            for (int k8 = 0; k8 < 16; k8++) {
                const int kb = k8 * 8;
                uint32_t af[2][4];
#pragma unroll
                for (int mf = 0; mf < 2; mf++) {
                    int mb = wm + mf * 16;
                    af[mf][0] = hs[(mb + gid) * SPITCH + kb + tig];
                    af[mf][1] = hs[(mb + gid + 8) * SPITCH + kb + tig];
                    af[mf][2] = hs[(mb + gid) * SPITCH + kb + tig + 4];
                    af[mf][3] = hs[(mb + gid + 8) * SPITCH + kb + tig + 4];
                }
                uint32_t bf[2][2];
#pragma unroll
                for (int nf = 0; nf < 2; nf++) {
                    int nb = wn + nf * 8 + gid;
                    bf[nf][0] = ws[nb * SPITCH + kb + tig];
                    bf[nf][1] = ws[nb * SPITCH + kb + tig + 4];
                }
#pragma unroll
                for (int mf = 0; mf < 2; mf++)
#pragma unroll
                    for (int nf = 0; nf < 2; nf++)
                        mma_tf32(acc[mf][nf], af[mf], bf[nf]);
            }
            __syncthreads();
        }

        // write gate sums to smem
#pragma unroll
        for (int mf = 0; mf < 2; mf++)
#pragma unroll
            for (int nf = 0; nf < 2; nf++) {
                int row = wm + mf * 16 + gid;
                int col = wn + nf * 8 + 2 * tig;
                gates[row * 68 + col]           = acc[mf][nf][0];
                gates[row * 68 + col + 1]       = acc[mf][nf][1];
                gates[(row + 8) * 68 + col]     = acc[mf][nf][2];
                gates[(row + 8) * 68 + col + 1] = acc[mf][nf][3];
            }
        __syncthreads();

        // activation + state: 64 b x 16 u = 1024 pairs -> 4 per thread
#pragma unroll
        for (int i = 0; i < 4; i++) {
            int p = tid + 256 * i;
            int bl = p >> 4;
            int u = p & 15;
            int ug = u0 + u;
            const float* Pb = P + (size_t)bl * G_;
            float ig = gates[bl * 68 + u]      + Pb[ug];
            float fg = gates[bl * 68 + 16 + u] + Pb[N_ + ug];
            float gg = gates[bl * 68 + 32 + u] + Pb[2 * N_ + ug];
            float og = gates[bl * 68 + 48 + u] + Pb[3 * N_ + ug];
            ig = 1.0f / (1.0f + expf(-ig));
            fg = 1.0f / (1.0f + expf(-fg));
            gg = tanhf(gg);
            og = 1.0f / (1.0f + expf(-og));
            size_t ci = (size_t)bl * N_ + ug;
            float cn = fg * c[ci] + ig * gg;
            c[ci] = cn;
            float hn = og * tanhf(cn);
            h_next[ci] = hn;
            hist[(size_t)bl * 2 * N_ + ug] = hn;
        }
        grid_barrier(0, 128);
    }
}

// ---------------- persistent cell recurrence (tensor core) ----------------
// 128 blocks x 256 threads. u0 = bid*8 -> 32 gate cols. m64 n32 k1024.
__global__ __launch_bounds__(256, 1) void cell_mma_kernel(float* __restrict__ out)
{
    extern __shared__ uint32_t smem_u[];
    uint32_t* hs = smem_u;                       // [64][132]
    uint32_t* ws = smem_u + 64 * SPITCH;         // [32][132]
    float* gates = (float*)(smem_u + 96 * SPITCH);  // [64][36]

    const int u0 = blockIdx.x * 8;
    const uint32_t* Wt = g_Wt[2];
    float* c = g_c[2];

    const int tid = threadIdx.x;
    const int lane = tid & 31;
    const int wid = tid >> 5;
    const int gid = lane >> 2;
    const int tig = lane & 3;
    const int wm = (wid & 1) * 32;
    const int wn = (wid >> 1) * 8;

    const int r0 = tid >> 5;
    const int q = tid & 31;

    const uint32_t* wsrc[4];
#pragma unroll
    for (int i = 0; i < 4; i++) {
        int cc = r0 + 8 * i;          // col 0..31
        int gate = cc >> 3;
        int u = cc & 7;
        wsrc[i] = Wt + (size_t)(gate * N_ + u0 + u) * N_ + q * 4;
    }

    for (int s = 0; s < T_; s++) {
        const float* P = g_Pc + (size_t)s * B_ * G_;
        const float* h_prev = g_h[4 + (s & 1)];
        float* h_next = g_h[4 + ((s + 1) & 1)];

        float acc[2][4];
#pragma unroll
        for (int mf = 0; mf < 2; mf++)
#pragma unroll
            for (int j = 0; j < 4; j++) acc[mf][j] = 0.0f;

        for (int k0 = 0; k0 < N_; k0 += 128) {
#pragma unroll
            for (int i = 0; i < 8; i++) {
                int r = r0 + 8 * i;
                float4 v = *(const float4*)(h_prev + (size_t)r * N_ + k0 + q * 4);
                uint4 u;
                u.x = f2tf32(v.x); u.y = f2tf32(v.y); u.z = f2tf32(v.z); u.w = f2tf32(v.w);
                *(uint4*)&hs[r * SPITCH + q * 4] = u;
            }
#pragma unroll
            for (int i = 0; i < 4; i++) {
                int cc = r0 + 8 * i;
                uint4 u = *(const uint4*)(wsrc[i] + k0);
                *(uint4*)&ws[cc * SPITCH + q * 4] = u;
            }
            __syncthreads();

#pragma unroll
            for (int k8 = 0; k8 < 16; k8++) {
                const int kb = k8 * 8;
                uint32_t af[2][4];
#pragma unroll
                for (int mf = 0; mf < 2; mf++) {
                    int mb = wm + mf * 16;
                    af[mf][0] = hs[(mb + gid) * SPITCH + kb + tig];
                    af[mf][1] = hs[(mb + gid + 8) * SPITCH + kb + tig];
                    af[mf][2] = hs[(mb + gid) * SPITCH + kb + tig + 4];
                    af[mf][3] = hs[(mb + gid + 8) * SPITCH + kb + tig + 4];
                }
                uint32_t bf[2];
                int nb = wn + gid;
                bf[0] = ws[nb * SPITCH + kb + tig];
                bf[1] = ws[nb * SPITCH + kb + tig + 4];
#pragma unroll
                for (int mf = 0; mf < 2; mf++)
                    mma_tf32(acc[mf], af[mf], bf);
            }
            __syncthreads();
        }

#pragma unroll
        for (int mf = 0; mf < 2; mf++) {
            int row = wm + mf * 16 + gid;
            int col = wn + 2 * tig;
            gates[row * 36 + col]           = acc[mf][0];
            gates[row * 36 + col + 1]       = acc[mf][1];
            gates[(row + 8) * 36 + col]     = acc[mf][2];
            gates[(row + 8) * 36 + col + 1] = acc[mf][3];
        }
        __syncthreads();

        // activation: 64 b x 8 u = 512 pairs -> 2 per thread
#pragma unroll
        for (int i = 0; i < 2; i++) {
            int p = tid + 256 * i;
            int bl = p >> 3;
            int u = p & 7;
            int ug = u0 + u;
            const float* Pb = P + (size_t)bl * G_;
            float ig = gates[bl * 36 + u]      + Pb[ug];
            float fg = gates[bl * 36 + 8 + u]  + Pb[N_ + ug];
            float gg = gates[bl * 36 + 16 + u] + Pb[2 * N_ + ug];
            float og = gates[bl * 36 + 24 + u] + Pb[3 * N_ + ug];
            ig = 1.0f / (1.0f + expf(-ig));
            fg = 1.0f / (1.0f + expf(-fg));
            gg = tanhf(gg);
            og = 1.0f / (1.0f + expf(-og));
            size_t ci = (size_t)bl * N_ + ug;
            float cn = fg * c[ci] + ig * gg;
            c[ci] = cn;
            float hn = og * tanhf(cn);
            h_next[ci] = hn;
            out[((size_t)bl * T_ + s) * N_ + ug] = hn;
        }
        grid_barrier(1, 128);
    }

    // tail: (hT, cT). Final h in g_h[4] (512 even), c in g_c[2].
    const size_t tail = (size_t)B_ * T_ * N_;
    const int HS = B_ * N_;
#pragma unroll
    for (int i = 0; i < 2; i++) {
        int idx = blockIdx.x * 256 + tid + 32768 * i;
        out[tail + idx] = g_h[4][idx];
        out[tail + HS + idx] = g_c[2][idx];
    }
}

// ---------------- host launcher ----------------
extern "C" void kernel_launch(void* const* d_in, const int* in_sizes, int n_in,
                              void* d_out, int out_size) {
    (void)in_sizes; (void)n_in; (void)out_size;
    const float* x     = (const float*)d_in[0];
    const float* Wf_ih = (const float*)d_in[1];
    const float* Wf_hh = (const float*)d_in[2];
    const float* bf    = (const float*)d_in[3];
    const float* Wb_ih = (const float*)d_in[4];
    const float* Wb_hh = (const float*)d_in[5];
    const float* bb    = (const float*)d_in[6];
    const float* Wc_ih = (const float*)d_in[7];
    const float* Wc_hh = (const float*)d_in[8];
    const float* bc    = (const float*)d_in[9];
    float* out = (float*)d_out;

    const int bilstm_smem = (2 * 64 * SPITCH) * 4 + 64 * 68 * 4;   // 84992
    const int cell_smem   = (96 * SPITCH) * 4 + 64 * 36 * 4;       // 59904
    cudaFuncSetAttribute(bilstm_mma_kernel, cudaFuncAttributeMaxDynamicSharedMemorySize, bilstm_smem);
    cudaFuncSetAttribute(cell_mma_kernel, cudaFuncAttributeMaxDynamicSharedMemorySize, cell_smem);

    // 1) zero recurrent state + convert W_hh to tf32
    zero_state_kernel<<<(6 * B_ * N_ + 511) / 512, 512>>>();
    wconv_kernel<<<dim3((G_ * N_ / 4) / 256, 3), 256>>>(Wf_hh, Wb_hh, Wc_hh);

    // 2) input projections (tf32 tensor core)
    dim3 ggrid(G_ / 64, (T_ * B_) / 128);
    gemm_tf32_kernel<<<ggrid, 256>>>(x, Wf_ih, bf, N_, 1, 0);
    gemm_tf32_kernel<<<ggrid, 256>>>(x, Wb_ih, bb, N_, 1, 1);

    // 3) bilstm recurrence (persistent, tensor core)
    bilstm_mma_kernel<<<128, 256, bilstm_smem>>>();

    // 4) cell input projection over bilstm output (K = 2N)
    gemm_tf32_kernel<<<ggrid, 256>>>(nullptr, Wc_ih, bc, 2 * N_, 2, 2);

    // 5) cell recurrence (persistent) + output + tail
    cell_mma_kernel<<<128, 256, cell_smem>>>(out);
}

// round 4
// speedup vs baseline: 2.6829x; 1.1852x over previous
#include <cuda_runtime.h>
#include <cstdint>
#include <math.h>

#define T_ 512
#define B_ 64
#define N_ 1024
#define G_ 4096   // 4*N

// ---------------- static device scratch ----------------
__device__ float g_Pf[(size_t)T_ * B_ * G_];
__device__ float g_Pb[(size_t)T_ * B_ * G_];
__device__ float g_Pc[(size_t)T_ * B_ * G_];
__device__ float g_bi[(size_t)T_ * B_ * 2 * N_];
__device__ float g_h[6][B_ * N_];
__device__ float g_c[3][B_ * N_];
__device__ uint32_t g_WihT[16 * 1024 * 1024];          // tf32 W_ih: f(4M) b(4M) c(8M)
__device__ uint32_t g_Wsw_bi[2 * 64 * 64 * 1024];      // swizzled tf32 W_hh fwd/bwd
__device__ uint32_t g_Wsw_c[128 * 32 * 1024];          // swizzled tf32 W_hh cell

__device__ unsigned g_barc[2] = {0, 0};
__device__ unsigned g_barg[2] = {0, 0};

__device__ __forceinline__ void grid_barrier(int which, unsigned nb) {
    __syncthreads();
    if (threadIdx.x == 0) {
        __threadfence();
        volatile unsigned* gen = &g_barg[which];
        unsigned g = *gen;
        if (atomicAdd(&g_barc[which], 1) == nb - 1) {
            g_barc[which] = 0;
            __threadfence();
            atomicExch((unsigned*)gen, g + 1);
        } else {
            while (*gen == g) { __nanosleep(64); }
            __threadfence();
        }
    }
    __syncthreads();
}

__global__ void zero_state_kernel() {
    int i = blockIdx.x * blockDim.x + threadIdx.x;
    if (i < 6 * B_ * N_) ((float*)g_h)[i] = 0.0f;
    if (i < 3 * B_ * N_) ((float*)g_c)[i] = 0.0f;
}

// ---------------- tf32 / mma / cp.async helpers ----------------
__device__ __forceinline__ uint32_t f2tf32(float x) {
    uint32_t r;
    asm("cvt.rna.tf32.f32 %0, %1;" : "=r"(r) : "f"(x));
    return r;
}
__device__ __forceinline__ void mma_tf32(float* c, const uint32_t* a, const uint32_t* b) {
    asm volatile(
        "mma.sync.aligned.m16n8k8.row.col.f32.tf32.tf32.f32 "
        "{%0,%1,%2,%3}, {%4,%5,%6,%7}, {%8,%9}, {%0,%1,%2,%3};"
        : "+f"(c[0]), "+f"(c[1]), "+f"(c[2]), "+f"(c[3])
        : "r"(a[0]), "r"(a[1]), "r"(a[2]), "r"(a[3]), "r"(b[0]), "r"(b[1]));
}
__device__ __forceinline__ void cp16(uint32_t dst, const void* src) {
    asm volatile("cp.async.cg.shared.global [%0], [%1], 16;" :: "r"(dst), "l"(src));
}
__device__ __forceinline__ void cp_commit() { asm volatile("cp.async.commit_group;"); }
template <int NN> __device__ __forceinline__ void cp_wait() {
    asm volatile("cp.async.wait_group %0;" :: "n"(NN));
}

// ---------------- one-time W_ih conversion (flat tf32 copy) ----------------
// 4M uint4 tasks: [0,1M) f, [1M,2M) b, [2M,4M) c
__global__ void wconv_ih_kernel(const float* __restrict__ Wf,
                                const float* __restrict__ Wb,
                                const float* __restrict__ Wc) {
    size_t i = (size_t)blockIdx.x * blockDim.x + threadIdx.x;
    const float* src;
    size_t off;
    if (i < (1u << 20))      { src = Wf; off = i; }
    else if (i < (2u << 20)) { src = Wb; off = i - (1u << 20); }
    else                     { src = Wc; off = i - (2u << 20); }
    float4 v = ((const float4*)src)[off];
    uint4 u;
    u.x = f2tf32(v.x); u.y = f2tf32(v.y); u.z = f2tf32(v.z); u.w = f2tf32(v.w);
    ((uint4*)g_WihT)[i] = u;
}

// ---------------- one-time W_hh fragment swizzles ----------------
// bilstm: per (dir,ublk) region of 65536 u32:
// idx = k16*1024 + nw*256 + nf*128 + lane*4 + kp*2 + r
__global__ void wswz_bi_kernel(const float* __restrict__ Wf,
                               const float* __restrict__ Wb) {
    size_t idx = (size_t)blockIdx.x * blockDim.x + threadIdx.x;
    unsigned region = idx >> 16;
    unsigned w = idx & 65535;
    int dir = region >> 6, ublk = region & 63;
    int r = w & 1, kp = (w >> 1) & 1, lane = (w >> 2) & 31;
    int nf = (w >> 7) & 1, nw = (w >> 8) & 3, k16 = (w >> 10) & 63;
    int gid = lane >> 2, tig = lane & 3;
    int col = nw * 16 + nf * 8 + gid;
    int gate = col >> 4, u = col & 15;
    int row = gate * N_ + ublk * 16 + u;
    int k = k16 * 16 + kp * 8 + r * 4 + tig;
    const float* W = dir ? Wb : Wf;
    g_Wsw_bi[idx] = f2tf32(W[(size_t)row * N_ + k]);
}
// cell: per block region of 32768 u32:
// idx = k16*512 + nw*128 + lane*4 + kp*2 + r
__global__ void wswz_cell_kernel(const float* __restrict__ Wc) {
    size_t idx = (size_t)blockIdx.x * blockDim.x + threadIdx.x;
    unsigned blk = idx >> 15;
    unsigned w = idx & 32767;
    int r = w & 1, kp = (w >> 1) & 1, lane = (w >> 2) & 31;
    int nw = (w >> 7) & 3, k16 = (w >> 9) & 63;
    int gid = lane >> 2, tig = lane & 3;
    int col = nw * 8 + gid;
    int gate = col >> 3, u = col & 7;
    int row = gate * N_ + blk * 8 + u;
    int k = k16 * 16 + kp * 8 + r * 4 + tig;
    g_Wsw_c[idx] = f2tf32(Wc[(size_t)row * N_ + k]);
}

// ---------------- tf32 GEMM v2: 128x128x16, cp.async double buffered ----------------
// C[m][g] = sum_k A[m][k]*W[g][k] + bias[g]. W already tf32 (g_WihT+woff).
// a_mode==1: m=(t*64+b) -> A row (b*512+t). a_mode==2: A=g_bi.
__global__ __launch_bounds__(256, 2) void gemm_tf32_kernel(
    const float* __restrict__ Aext,
    const uint32_t* __restrict__ Wt,
    const float* __restrict__ bias,
    int K, int a_mode, int dst_sel)
{
    float* C = (dst_sel == 0) ? g_Pf : (dst_sel == 1) ? g_Pb : g_Pc;
    const float* A = (a_mode == 2) ? (const float*)g_bi : Aext;

    __shared__ __align__(16) float As[2][128 * 20];
    __shared__ __align__(16) uint32_t Ws[2][128 * 20];

    const int tid = threadIdx.x;
    const int m0 = blockIdx.y * 128;
    const int g0 = blockIdx.x * 128;

    // loaders: rows tid>>2 and +64, quad tid&3
    const int lr = tid >> 2;
    const int lq = tid & 3;
    const float* asrc[2];
    const uint32_t* wsrc[2];
#pragma unroll
    for (int i = 0; i < 2; i++) {
        int m = m0 + lr + 64 * i;
        int prow = (a_mode == 1) ? ((m & 63) * T_ + (m >> 6)) : m;
        asrc[i] = A + (size_t)prow * K + lq * 4;
        wsrc[i] = Wt + (size_t)(g0 + lr + 64 * i) * K + lq * 4;
    }
    uint32_t asm_base[2][2], wsm_base[2][2];
#pragma unroll
    for (int bufi = 0; bufi < 2; bufi++)
#pragma unroll
        for (int i = 0; i < 2; i++) {
            asm_base[bufi][i] = (uint32_t)__cvta_generic_to_shared(&As[bufi][(lr + 64 * i) * 20 + lq * 4]);
            wsm_base[bufi][i] = (uint32_t)__cvta_generic_to_shared(&Ws[bufi][(lr + 64 * i) * 20 + lq * 4]);
        }

    const int lane = tid & 31;
    const int wid = tid >> 5;
    const int gid = lane >> 2;
    const int tig = lane & 3;
    const int wm = (wid & 3) * 32;
    const int wn = (wid >> 2) * 64;

    float acc[2][8][4];
#pragma unroll
    for (int mf = 0; mf < 2; mf++)
#pragma unroll
        for (int nf = 0; nf < 8; nf++)
#pragma unroll
            for (int j = 0; j < 4; j++) acc[mf][nf][j] = 0.0f;

    const int NC = K / 16;
    // preload chunk 0
#pragma unroll
    for (int i = 0; i < 2; i++) {
        cp16(asm_base[0][i], asrc[i]);
        cp16(wsm_base[0][i], wsrc[i]);
    }
    cp_commit();

    for (int ch = 0; ch < NC; ch++) {
        const int buf = ch & 1;
        if (ch + 1 < NC) {
            const int nb = (ch + 1) & 1;
            const int k0 = (ch + 1) * 16;
#pragma unroll
            for (int i = 0; i < 2; i++) {
                cp16(asm_base[nb][i], asrc[i] + k0);
                cp16(wsm_base[nb][i], wsrc[i] + k0);
            }
            cp_commit();
            cp_wait<1>();
        } else {
            cp_wait<0>();
        }
        __syncthreads();

        const float* Af = As[buf];
        const uint32_t* Wf = Ws[buf];
#pragma unroll
        for (int ks = 0; ks < 2; ks++) {
            const int kb = ks * 8;
            uint32_t af[2][4];
#pragma unroll
            for (int mf = 0; mf < 2; mf++) {
                int mb = wm + mf * 16;
                af[mf][0] = f2tf32(Af[(mb + gid) * 20 + kb + tig]);
                af[mf][1] = f2tf32(Af[(mb + gid + 8) * 20 + kb + tig]);
                af[mf][2] = f2tf32(Af[(mb + gid) * 20 + kb + tig + 4]);
                af[mf][3] = f2tf32(Af[(mb + gid + 8) * 20 + kb + tig + 4]);
            }
            uint32_t bf[8][2];
#pragma unroll
            for (int nf = 0; nf < 8; nf++) {
                int nb2 = wn + nf * 8 + gid;
                bf[nf][0] = Wf[nb2 * 20 + kb + tig];
                bf[nf][1] = Wf[nb2 * 20 + kb + tig + 4];
            }
#pragma unroll
            for (int mf = 0; mf < 2; mf++)
#pragma unroll
                for (int nf = 0; nf < 8; nf++)
                    mma_tf32(acc[mf][nf], af[mf], bf[nf]);
        }
        __syncthreads();
    }

#pragma unroll
    for (int mf = 0; mf < 2; mf++) {
#pragma unroll
        for (int nf = 0; nf < 8; nf++) {
            int row = m0 + wm + mf * 16 + gid;
            int col = g0 + wn + nf * 8 + 2 * tig;
            float b0 = bias[col], b1 = bias[col + 1];
            float2 v0 = make_float2(acc[mf][nf][0] + b0, acc[mf][nf][1] + b1);
            float2 v1 = make_float2(acc[mf][nf][2] + b0, acc[mf][nf][3] + b1);
            *(float2*)&C[(size_t)row * G_ + col] = v0;
            *(float2*)&C[(size_t)(row + 8) * G_ + col] = v1;
        }
    }
}

// ---------------- persistent bilstm recurrence (W fragments direct from gmem) ----------------
#define SPITCH 132
__global__ __launch_bounds__(256, 1) void bilstm_mma_kernel()
{
    extern __shared__ uint32_t smem_u[];
    uint32_t* hs = smem_u;                               // [64][132]
    float* gates = (float*)(smem_u + 64 * SPITCH);       // [64][68]

    const int bid = blockIdx.x;
    const int dir = bid >> 6;
    const int u0 = (bid & 63) * 16;
    const float* Pbase = dir ? g_Pb : g_Pf;
    float* c = g_c[dir];

    const int tid = threadIdx.x;
    const int lane = tid & 31;
    const int wid = tid >> 5;
    const int gid = lane >> 2;
    const int tig = lane & 3;
    const int wm = (wid & 1) * 32;
    const int wn = (wid >> 1) * 16;
    const int nw = wid >> 1;

    const int r0 = tid >> 5;
    const int q = tid & 31;

    // swizzled W pointer: region (dir*64 + ublk)*65536; per-thread offset
    const uint32_t* wp = g_Wsw_bi + ((size_t)(dir * 64 + (bid & 63)) << 16)
                       + (nw * 64 + lane) * 4;           // nf0; nf1 at +128

    for (int s = 0; s < T_; s++) {
        const int t = dir ? (T_ - 1 - s) : s;
        const float* P = Pbase + (size_t)t * B_ * G_;
        const float* h_prev = g_h[2 * dir + (s & 1)];
        float* h_next = g_h[2 * dir + ((s + 1) & 1)];
        float* hist = g_bi + (size_t)t * B_ * 2 * N_ + dir * N_;

        float acc[2][2][4];
#pragma unroll
        for (int mf = 0; mf < 2; mf++)
#pragma unroll
            for (int nf = 0; nf < 2; nf++)
#pragma unroll
                for (int j = 0; j < 4; j++) acc[mf][nf][j] = 0.0f;

        uint4 wa = *(const uint4*)(wp);
        uint4 wb = *(const uint4*)(wp + 128);

        for (int ch = 0; ch < 8; ch++) {
            // load h chunk: 64 rows x 128 k
#pragma unroll
            for (int i = 0; i < 8; i++) {
                int r = r0 + 8 * i;
                float4 v = *(const float4*)(h_prev + (size_t)r * N_ + ch * 128 + q * 4);
                uint4 u;
                u.x = f2tf32(v.x); u.y = f2tf32(v.y); u.z = f2tf32(v.z); u.w = f2tf32(v.w);
                *(uint4*)&hs[r * SPITCH + q * 4] = u;
            }
            __syncthreads();

#pragma unroll
            for (int k16l = 0; k16l < 8; k16l++) {
                int g16 = ch * 8 + k16l;
                int ng = (g16 + 1 < 64) ? g16 + 1 : g16;
                uint4 na = *(const uint4*)(wp + (size_t)ng * 1024);
                uint4 nb = *(const uint4*)(wp + 128 + (size_t)ng * 1024);

#pragma unroll
                for (int kp = 0; kp < 2; kp++) {
                    const int kb = k16l * 16 + kp * 8;
                    uint32_t af[2][4];
#pragma unroll
                    for (int mf = 0; mf < 2; mf++) {
                        int mb = wm + mf * 16;
                        af[mf][0] = hs[(mb + gid) * SPITCH + kb + tig];
                        af[mf][1] = hs[(mb + gid + 8) * SPITCH + kb + tig];
                        af[mf][2] = hs[(mb + gid) * SPITCH + kb + tig + 4];
                        af[mf][3] = hs[(mb + gid + 8) * SPITCH + kb + tig + 4];
                    }
                    uint32_t bf0[2], bf1[2];
                    if (kp == 0) { bf0[0] = wa.x; bf0[1] = wa.y; bf1[0] = wb.x; bf1[1] = wb.y; }
                    else         { bf0[0] = wa.z; bf0[1] = wa.w; bf1[0] = wb.z; bf1[1] = wb.w; }
#pragma unroll
                    for (int mf = 0; mf < 2; mf++) {
                        mma_tf32(acc[mf][0], af[mf], bf0);
                        mma_tf32(acc[mf][1], af[mf], bf1);
                    }
                }
                wa = na; wb = nb;
            }
            __syncthreads();
        }

#pragma unroll
        for (int mf = 0; mf < 2; mf++)
#pragma unroll
            for (int nf = 0; nf < 2; nf++) {
                int row = wm + mf * 16 + gid;
                int col = wn + nf * 8 + 2 * tig;
                gates[row * 68 + col]           = acc[mf][nf][0];
                gates[row * 68 + col + 1]       = acc[mf][nf][1];
                gates[(row + 8) * 68 + col]     = acc[mf][nf][2];
                gates[(row + 8) * 68 + col + 1] = acc[mf][nf][3];
            }
        __syncthreads();

#pragma unroll
        for (int i = 0; i < 4; i++) {
            int p = tid + 256 * i;
            int bl = p >> 4;
            int u = p & 15;
            int ug = u0 + u;
            const float* Pb = P + (size_t)bl * G_;
            float ig = gates[bl * 68 + u]      + Pb[ug];
            float fg = gates[bl * 68 + 16 + u] + Pb[N_ + ug];
            float gg = gates[bl * 68 + 32 + u] + Pb[2 * N_ + ug];
            float og = gates[bl * 68 + 48 + u] + Pb[3 * N_ + ug];
            ig = 1.0f / (1.0f + expf(-ig));
            fg = 1.0f / (1.0f + expf(-fg));
            gg = tanhf(gg);
            og = 1.0f / (1.0f + expf(-og));
            size_t ci = (size_t)bl * N_ + ug;
            float cn = fg * c[ci] + ig * gg;
            c[ci] = cn;
            float hn = og * tanhf(cn);
            h_next[ci] = hn;
            hist[(size_t)bl * 2 * N_ + ug] = hn;
        }
        grid_barrier(0, 128);
    }
}

// ---------------- persistent cell recurrence ----------------
__global__ __launch_bounds__(256, 1) void cell_mma_kernel(float* __restrict__ out)
{
    extern __shared__ uint32_t smem_u[];
    uint32_t* hs = smem_u;                               // [64][132]
    float* gates = (float*)(smem_u + 64 * SPITCH);       // [64][36]

    const int u0 = blockIdx.x * 8;
    float* c = g_c[2];

    const int tid = threadIdx.x;
    const int lane = tid & 31;
    const int wid = tid >> 5;
    const int gid = lane >> 2;
    const int tig = lane & 3;
    const int wm = (wid & 1) * 32;
    const int wn = (wid >> 1) * 8;
    const int nw = wid >> 1;

    const int r0 = tid >> 5;
    const int q = tid & 31;

    const uint32_t* wp = g_Wsw_c + ((size_t)blockIdx.x << 15) + (nw * 32 + lane) * 4;

    for (int s = 0; s < T_; s++) {
        const float* P = g_Pc + (size_t)s * B_ * G_;
        const float* h_prev = g_h[4 + (s & 1)];
        float* h_next = g_h[4 + ((s + 1) & 1)];

        float acc[2][4];
#pragma unroll
        for (int mf = 0; mf < 2; mf++)
#pragma unroll
            for (int j = 0; j < 4; j++) acc[mf][j] = 0.0f;

        uint4 wa = *(const uint4*)(wp);

        for (int ch = 0; ch < 8; ch++) {
#pragma unroll
            for (int i = 0; i < 8; i++) {
                int r = r0 + 8 * i;
                float4 v = *(const float4*)(h_prev + (size_t)r * N_ + ch * 128 + q * 4);
                uint4 u;
                u.x = f2tf32(v.x); u.y = f2tf32(v.y); u.z = f2tf32(v.z); u.w = f2tf32(v.w);
                *(uint4*)&hs[r * SPITCH + q * 4] = u;
            }
            __syncthreads();

#pragma unroll
            for (int k16l = 0; k16l < 8; k16l++) {
                int g16 = ch * 8 + k16l;
                int ng = (g16 + 1 < 64) ? g16 + 1 : g16;
                uint4 na = *(const uint4*)(wp + (size_t)ng * 512);

#pragma unroll
                for (int kp = 0; kp < 2; kp++) {
                    const int kb = k16l * 16 + kp * 8;
                    uint32_t af[2][4];
#pragma unroll
                    for (int mf = 0; mf < 2; mf++) {
                        int mb = wm + mf * 16;
                        af[mf][0] = hs[(mb + gid) * SPITCH + kb + tig];
                        af[mf][1] = hs[(mb + gid + 8) * SPITCH + kb + tig];
                        af[mf][2] = hs[(mb + gid) * SPITCH + kb + tig + 4];
                        af[mf][3] = hs[(mb + gid + 8) * SPITCH + kb + tig + 4];
                    }
                    uint32_t bf[2];
                    if (kp == 0) { bf[0] = wa.x; bf[1] = wa.y; }
                    else         { bf[0] = wa.z; bf[1] = wa.w; }
#pragma unroll
                    for (int mf = 0; mf < 2; mf++)
                        mma_tf32(acc[mf], af[mf], bf);
                }
                wa = na;
            }
            __syncthreads();
        }

#pragma unroll
        for (int mf = 0; mf < 2; mf++) {
            int row = wm + mf * 16 + gid;
            int col = wn + 2 * tig;
            gates[row * 36 + col]           = acc[mf][0];
            gates[row * 36 + col + 1]       = acc[mf][1];
            gates[(row + 8) * 36 + col]     = acc[mf][2];
            gates[(row + 8) * 36 + col + 1] = acc[mf][3];
        }
        __syncthreads();

#pragma unroll
        for (int i = 0; i < 2; i++) {
            int p = tid + 256 * i;
            int bl = p >> 3;
            int u = p & 7;
            int ug = u0 + u;
            const float* Pb = P + (size_t)bl * G_;
            float ig = gates[bl * 36 + u]      + Pb[ug];
            float fg = gates[bl * 36 + 8 + u]  + Pb[N_ + ug];
            float gg = gates[bl * 36 + 16 + u] + Pb[2 * N_ + ug];
            float og = gates[bl * 36 + 24 + u] + Pb[3 * N_ + ug];
            ig = 1.0f / (1.0f + expf(-ig));
            fg = 1.0f / (1.0f + expf(-fg));
            gg = tanhf(gg);
            og = 1.0f / (1.0f + expf(-og));
            size_t ci = (size_t)bl * N_ + ug;
            float cn = fg * c[ci] + ig * gg;
            c[ci] = cn;
            float hn = og * tanhf(cn);
            h_next[ci] = hn;
            out[((size_t)bl * T_ + s) * N_ + ug] = hn;
        }
        grid_barrier(1, 128);
    }

    const size_t tail = (size_t)B_ * T_ * N_;
    const int HS = B_ * N_;
#pragma unroll
    for (int i = 0; i < 2; i++) {
        int idx = blockIdx.x * 256 + tid + 32768 * i;
        out[tail + idx] = g_h[4][idx];
        out[tail + HS + idx] = g_c[2][idx];
    }
}

// ---------------- host launcher ----------------
extern "C" void kernel_launch(void* const* d_in, const int* in_sizes, int n_in,
                              void* d_out, int out_size) {
    (void)in_sizes; (void)n_in; (void)out_size;
    const float* x     = (const float*)d_in[0];
    const float* Wf_ih = (const float*)d_in[1];
    const float* Wf_hh = (const float*)d_in[2];
    const float* bf    = (const float*)d_in[3];
    const float* Wb_ih = (const float*)d_in[4];
    const float* Wb_hh = (const float*)d_in[5];
    const float* bb    = (const float*)d_in[6];
    const float* Wc_ih = (const float*)d_in[7];
    const float* Wc_hh = (const float*)d_in[8];
    const float* bc    = (const float*)d_in[9];
    float* out = (float*)d_out;

    uint32_t* wih;
    cudaGetSymbolAddress((void**)&wih, g_WihT);
    const uint32_t* wih_f = wih;
    const uint32_t* wih_b = wih + (4u << 20);
    const uint32_t* wih_c = wih + (8u << 20);

    const int bilstm_smem = 64 * SPITCH * 4 + 64 * 68 * 4;  // 51200
    const int cell_smem   = 64 * SPITCH * 4 + 64 * 36 * 4;  // 43008
    cudaFuncSetAttribute(bilstm_mma_kernel, cudaFuncAttributeMaxDynamicSharedMemorySize, bilstm_smem);
    cudaFuncSetAttribute(cell_mma_kernel, cudaFuncAttributeMaxDynamicSharedMemorySize, cell_smem);

    // 1) init + one-time weight prep
    zero_state_kernel<<<(6 * B_ * N_ + 511) / 512, 512>>>();
    wconv_ih_kernel<<<(4 << 20) / 256, 256>>>(Wf_ih, Wb_ih, Wc_ih);
    wswz_bi_kernel<<<(8 << 20) / 256, 256>>>(Wf_hh, Wb_hh);
    wswz_cell_kernel<<<(4 << 20) / 256, 256>>>(Wc_hh);

    // 2) input projections
    dim3 ggrid(G_ / 128, (T_ * B_) / 128);
    gemm_tf32_kernel<<<ggrid, 256>>>(x, wih_f, bf, N_, 1, 0);
    gemm_tf32_kernel<<<ggrid, 256>>>(x, wih_b, bb, N_, 1, 1);

    // 3) bilstm recurrence
    bilstm_mma_kernel<<<128, 256, bilstm_smem>>>();

    // 4) cell input projection (K = 2N)
    gemm_tf32_kernel<<<ggrid, 256>>>(nullptr, wih_c, bc, 2 * N_, 2, 2);

    // 5) cell recurrence + output
    cell_mma_kernel<<<128, 256, cell_smem>>>(out);
}